// round 12
// baseline (speedup 1.0000x reference)
#include <cuda_runtime.h>
#include <cuda_fp16.h>

#define B 512
#define D 128
#define JT 64            // j per block
#define IB 2             // i per block
#define NH_BYTES (IB * D * JT * 2)   // 32768 per buffer

// ---------------- device scratch (no allocation allowed) ----------------
__device__ float  g_e1n[3][B][D];     // normalized emb1, row-major [l][i][d]
__device__ __half g_e2nTh[3][D][B];   // normalized emb2, fp16, transposed [l][d][j]
__device__ float  g_c1p[2][B][D];     // cert1_{1,2} * 0.5*alpha_{1,2}
__device__ __half g_c2Th[2][D][B];    // cert2_{1,2}, fp16, transposed [l][d][j]
__device__ float  g_bp[2][D];         // 0.5*beta_{1,2}
__device__ uint4  g_wH[2][D];         // .x/.y/.z = broadcast half2 of w0..w2, .w = packed idx

__device__ __forceinline__ __half2 u2h(unsigned x) {
    __half2 h; *(unsigned*)&h = x; return h;
}
__device__ __forceinline__ unsigned h2u(__half2 h) {
    return *(unsigned*)&h;
}
__device__ __forceinline__ __half2 tanh2(__half2 x) {
    unsigned xi = h2u(x), yo;
    asm("tanh.approx.f16x2 %0, %1;" : "=r"(yo) : "r"(xi));
    return u2h(yo);
}
// r = s + P*(n-s),  n = (a-e2)^2,  P = 0.5*tanh(cp*c2+bp)+0.5   (all half2)
__device__ __forceinline__ __half2 blend2(__half2 ha, __half2 e2, __half2 cp,
                                          __half2 c2, __half2 bp, __half2 s,
                                          __half2 H05) {
    __half2 v = __hsub2(ha, e2);
    __half2 n = __hmul2(v, v);
    __half2 P = __hfma2(H05, tanh2(__hfma2(cp, c2, bp)), H05);
    return __hfma2(P, __hsub2(n, s), s);
}
// 3-term weighted sum of gathered half2s
__device__ __forceinline__ __half2 ws3(__half2 w0, __half2 w1, __half2 w2,
                                       unsigned a, unsigned b, unsigned c) {
    return __hfma2(w2, u2h(c), __hfma2(w1, u2h(b), __hmul2(w0, u2h(a))));
}

// ---------------- prep v2 (unchanged, proven) ----------------
__global__ __launch_bounds__(256) void prep_kernel(
    const float* __restrict__ e1_0, const float* __restrict__ e1_1, const float* __restrict__ e1_2,
    const float* __restrict__ e2_0, const float* __restrict__ e2_1, const float* __restrict__ e2_2,
    const float* __restrict__ c1_1, const float* __restrict__ c1_2,
    const float* __restrict__ c2_1, const float* __restrict__ c2_2,
    const float* __restrict__ a_1,  const float* __restrict__ a_2,
    const float* __restrict__ b_1,  const float* __restrict__ b_2,
    const float* __restrict__ link0, const float* __restrict__ link1)
{
    __shared__ float sm[64][129];
    __shared__ float part[4][64];
    __shared__ float sInv[64];

    const int bid = blockIdx.x;
    const int t   = threadIdx.x;

    if (bid < 40) {
        const bool isE = bid < 24;
        const int t2 = isE ? bid : bid - 24;
        const int l = t2 >> 3, rt = t2 & 7;
        const float* src = isE ? (l == 0 ? e2_0 : (l == 1 ? e2_1 : e2_2))
                               : (l == 0 ? c2_1 : c2_2);
        const int r0 = rt * 64;
        for (int idx = t; idx < 64 * 128; idx += 256) {
            int rr = idx >> 7, c = idx & 127;
            sm[rr][c] = src[(r0 + rr) * D + c];
        }
        __syncthreads();
        if (isE) {
            int qd = t >> 6, rr = t & 63;
            float ss = 0.f;
            #pragma unroll 8
            for (int c = qd * 32; c < qd * 32 + 32; ++c) {
                float x = sm[rr][c]; ss += x * x;
            }
            part[qd][rr] = ss;
            __syncthreads();
            if (t < 64) {
                float tot = part[0][t] + part[1][t] + part[2][t] + part[3][t];
                sInv[t] = 1.0f / fmaxf(sqrtf(tot), 1e-12f);
            }
        } else {
            if (t < 64) sInv[t] = 1.0f;
        }
        __syncthreads();
        __half (*dst)[B] = isE ? g_e2nTh[l] : g_c2Th[l];
        for (int idx = t; idx < 64 * 128; idx += 256) {
            int d2 = idx >> 6, rr = idx & 63;
            dst[d2][r0 + rr] = __float2half_rn(sm[rr][d2] * sInv[rr]);
        }
    } else if (bid < 232) {
        int rid = (bid - 40) * 8 + (t >> 5);
        int l = rid / 512, r = rid % 512;
        const float* src = (l == 0) ? e1_0 : (l == 1 ? e1_1 : e1_2);
        int lane = t & 31;
        float4 x = *(const float4*)&src[r * D + lane * 4];
        float ss = x.x * x.x + x.y * x.y + x.z * x.z + x.w * x.w;
        #pragma unroll
        for (int o = 16; o; o >>= 1) ss += __shfl_xor_sync(0xffffffffu, ss, o);
        float inv = 1.0f / fmaxf(sqrtf(ss), 1e-12f);
        float4 v = make_float4(x.x * inv, x.y * inv, x.z * inv, x.w * inv);
        *(float4*)&g_e1n[l][r][lane * 4] = v;
    } else if (bid < 296) {
        int base = (bid - 232) * 2048;
        #pragma unroll
        for (int k = 0; k < 8; ++k) {
            int idx = base + k * 256 + t;
            int l = idx >> 16;
            int rem = idx & 65535;
            int d2 = rem & 127;
            const float* c = l ? c1_2 : c1_1;
            const float* a = l ? a_2  : a_1;
            ((float*)g_c1p[l])[rem] = c[rem] * (0.5f * a[d2]);
        }
    } else if (bid == 296) {
        if (t < 128) {
            g_bp[0][t] = 0.5f * b_1[t];
            g_bp[1][t] = 0.5f * b_2[t];
        }
    } else {
        int m = bid - 297;
        if (t < 128) {
            int e = t;
            const float* L = m ? link1 : link0;
            float v0 = -1e30f, v1 = -1e30f, v2 = -1e30f;
            int   i0 = 0, i1 = 0, i2 = 0;
            for (int r = 0; r < D; ++r) {
                float w = L[r * D + e];
                if (w > v0)      { v2 = v1; i2 = i1; v1 = v0; i1 = i0; v0 = w; i0 = r; }
                else if (w > v1) { v2 = v1; i2 = i1; v1 = w;  i1 = r; }
                else if (w > v2) { v2 = w;  i2 = r; }
            }
            float inv = 1.0f / (v0 + v1 + v2 + 1e-8f);
            unsigned h0 = (unsigned)__half_as_ushort(__float2half_rn(v0 * inv));
            unsigned h1 = (unsigned)__half_as_ushort(__float2half_rn(v1 * inv));
            unsigned h2 = (unsigned)__half_as_ushort(__float2half_rn(v2 * inv));
            g_wH[m][e] = make_uint4(h0 * 0x10001u, h1 * 0x10001u, h2 * 0x10001u,
                                    (unsigned)i0 | ((unsigned)i1 << 8) | ((unsigned)i2 << 16));
        }
    }
}

// ---------------- fused similarity kernel v4 ----------------
// block = (8 j-octs, 64 channel-pairs) = 512 threads, 3 blocks/SM, IB=2 i-rows.
// Materialized layer-0 (nhA) + double-buffered layer-1 results (nhB) in 64 KB
// DYNAMIC smem; every e2/c2 LDG serves both i rows. All nh accesses LDS.128
// conflict-free (8-lane group = one full 128B row). Math half2 incl tanh.f16x2.
__global__ __launch_bounds__(512, 3) void avsl_main_kernel(float* __restrict__ out)
{
    extern __shared__ __align__(16) char dynsm[];
    __half (*nhA)[D][JT] = (__half (*)[D][JT])dynsm;                // 32 KB
    __half (*nhB)[D][JT] = (__half (*)[D][JT])(dynsm + NH_BYTES);   // 32 KB
    float4 (*sRed)[32]   = (float4 (*)[32])dynsm;                   // alias nhA (dead)

    __shared__ uint4    sW[2][D];      // 4 KB
    __shared__ unsigned sIh[5][IB][D]; // 5 KB: bcast half2 of e1n l0..2, c1p l1..2
    __shared__ unsigned sBPh[2][D];    // 1 KB

    const int q   = threadIdx.x;     // 0..7  (j-oct)
    const int g   = threadIdx.y;     // 0..63 (channel pair)
    const int tid = g * 8 + q;
    const int jj  = blockIdx.x * JT + q * 8;
    const int i0  = blockIdx.y * IB;

    if (tid < 2 * D) {
        ((uint4*)sW)[tid] = ((const uint4*)g_wH)[tid];
        ((unsigned*)sBPh)[tid] = h2u(__float2half2_rn(((const float*)g_bp)[tid]));
    }
    for (int t = tid; t < 5 * IB * D; t += 512) {
        int seg = t / (IB * D);
        int rem = t % (IB * D);
        int ii = rem >> 7, d = rem & 127;
        float v = (seg < 3) ? g_e1n[seg][i0 + ii][d] : g_c1p[seg - 3][i0 + ii][d];
        sIh[seg][ii][d] = h2u(__float2half2_rn(v));
    }
    __syncthreads();   // (1)

    const __half2 H05 = __float2half2_rn(0.5f);

    // ---- layer 0 -> nhA[ii] (one LDG per channel, shared by both i) ----
    #pragma unroll
    for (int k = 0; k < 2; ++k) {
        const int e = g * 2 + k;
        uint4 x = *(const uint4*)&g_e2nTh[0][e][jj];
        #pragma unroll
        for (int ii = 0; ii < IB; ++ii) {
            __half2 h = u2h(sIh[0][ii][e]);
            uint4 r;
            __half2 v;
            v = __hsub2(h, u2h(x.x)); r.x = h2u(__hmul2(v, v));
            v = __hsub2(h, u2h(x.y)); r.y = h2u(__hmul2(v, v));
            v = __hsub2(h, u2h(x.z)); r.z = h2u(__hmul2(v, v));
            v = __hsub2(h, u2h(x.w)); r.w = h2u(__hmul2(v, v));
            *(uint4*)&nhA[ii][e][q * 8] = r;
        }
    }
    __syncthreads();   // (2)

    // ---- layer 1: gather nhA -> write nhB (LDGs shared by both i) ----
    #pragma unroll
    for (int k = 0; k < 2; ++k) {
        const int e = g * 2 + k;
        const uint4 W = sW[0][e];
        const __half2 w0 = u2h(W.x), w1 = u2h(W.y), w2 = u2h(W.z);
        const int o0 = (int)(W.w & 255u) * 8;
        const int o1 = (int)((W.w >> 8) & 255u) * 8;
        const int o2 = (int)((W.w >> 16) & 255u) * 8;
        uint4 e2u = *(const uint4*)&g_e2nTh[1][e][jj];
        uint4 c2u = *(const uint4*)&g_c2Th[0][e][jj];
        const __half2 bp = u2h(sBPh[0][e]);
        #pragma unroll
        for (int ii = 0; ii < IB; ++ii) {
            const uint4* nb = (const uint4*)nhA[ii];
            uint4 r0 = nb[o0 + q], r1 = nb[o1 + q], r2 = nb[o2 + q];
            __half2 ha = u2h(sIh[1][ii][e]);
            __half2 cp = u2h(sIh[3][ii][e]);
            uint4 res;
            res.x = h2u(blend2(ha, u2h(e2u.x), cp, u2h(c2u.x), bp,
                               ws3(w0, w1, w2, r0.x, r1.x, r2.x), H05));
            res.y = h2u(blend2(ha, u2h(e2u.y), cp, u2h(c2u.y), bp,
                               ws3(w0, w1, w2, r0.y, r1.y, r2.y), H05));
            res.z = h2u(blend2(ha, u2h(e2u.z), cp, u2h(c2u.z), bp,
                               ws3(w0, w1, w2, r0.z, r1.z, r2.z), H05));
            res.w = h2u(blend2(ha, u2h(e2u.w), cp, u2h(c2u.w), bp,
                               ws3(w0, w1, w2, r0.w, r1.w, r2.w), H05));
            *(uint4*)&nhB[ii][e][q * 8] = res;
        }
    }
    __syncthreads();   // (3)

    // ---- layer 2: gather nhB + per-thread half2 accumulation ----
    __half2 acc[IB][4];
    #pragma unroll
    for (int ii = 0; ii < IB; ++ii)
        #pragma unroll
        for (int t = 0; t < 4; ++t) acc[ii][t] = u2h(0u);
    #pragma unroll
    for (int k = 0; k < 2; ++k) {
        const int e = g * 2 + k;
        const uint4 W = sW[1][e];
        const __half2 w0 = u2h(W.x), w1 = u2h(W.y), w2 = u2h(W.z);
        const int o0 = (int)(W.w & 255u) * 8;
        const int o1 = (int)((W.w >> 8) & 255u) * 8;
        const int o2 = (int)((W.w >> 16) & 255u) * 8;
        uint4 e2u = *(const uint4*)&g_e2nTh[2][e][jj];
        uint4 c2u = *(const uint4*)&g_c2Th[1][e][jj];
        const __half2 bp = u2h(sBPh[1][e]);
        #pragma unroll
        for (int ii = 0; ii < IB; ++ii) {
            const uint4* nb = (const uint4*)nhB[ii];
            uint4 r0 = nb[o0 + q], r1 = nb[o1 + q], r2 = nb[o2 + q];
            __half2 ha = u2h(sIh[2][ii][e]);
            __half2 cp = u2h(sIh[4][ii][e]);
            acc[ii][0] = __hadd2(acc[ii][0],
                blend2(ha, u2h(e2u.x), cp, u2h(c2u.x), bp,
                       ws3(w0, w1, w2, r0.x, r1.x, r2.x), H05));
            acc[ii][1] = __hadd2(acc[ii][1],
                blend2(ha, u2h(e2u.y), cp, u2h(c2u.y), bp,
                       ws3(w0, w1, w2, r0.y, r1.y, r2.y), H05));
            acc[ii][2] = __hadd2(acc[ii][2],
                blend2(ha, u2h(e2u.z), cp, u2h(c2u.z), bp,
                       ws3(w0, w1, w2, r0.z, r1.z, r2.z), H05));
            acc[ii][3] = __hadd2(acc[ii][3],
                blend2(ha, u2h(e2u.w), cp, u2h(c2u.w), bp,
                       ws3(w0, w1, w2, r0.w, r1.w, r2.w), H05));
        }
    }
    __syncthreads();   // (4) — nhA dead since (3): sRed alias is safe

    // convert to fp32, fold the 4 channel-pair groups within each warp
    float4 aLo[IB], aHi[IB];
    #pragma unroll
    for (int ii = 0; ii < IB; ++ii) {
        float2 f0 = __half22float2(acc[ii][0]);
        float2 f1 = __half22float2(acc[ii][1]);
        float2 f2 = __half22float2(acc[ii][2]);
        float2 f3 = __half22float2(acc[ii][3]);
        aLo[ii] = make_float4(f0.x, f0.y, f1.x, f1.y);
        aHi[ii] = make_float4(f2.x, f2.y, f3.x, f3.y);
    }
    #pragma unroll
    for (int ii = 0; ii < IB; ++ii) {
        #pragma unroll
        for (int o = 16; o >= 8; o >>= 1) {
            aLo[ii].x += __shfl_down_sync(0xffffffffu, aLo[ii].x, o);
            aLo[ii].y += __shfl_down_sync(0xffffffffu, aLo[ii].y, o);
            aLo[ii].z += __shfl_down_sync(0xffffffffu, aLo[ii].z, o);
            aLo[ii].w += __shfl_down_sync(0xffffffffu, aLo[ii].w, o);
            aHi[ii].x += __shfl_down_sync(0xffffffffu, aHi[ii].x, o);
            aHi[ii].y += __shfl_down_sync(0xffffffffu, aHi[ii].y, o);
            aHi[ii].z += __shfl_down_sync(0xffffffffu, aHi[ii].z, o);
            aHi[ii].w += __shfl_down_sync(0xffffffffu, aHi[ii].w, o);
        }
    }
    const int w = tid >> 5, lane = tid & 31;
    if (lane < 8) {
        #pragma unroll
        for (int ii = 0; ii < IB; ++ii) {
            sRed[w][ii * 16 + lane * 2]     = aLo[ii];
            sRed[w][ii * 16 + lane * 2 + 1] = aHi[ii];
        }
    }
    __syncthreads();   // (5)
    if (tid < 32) {    // slot: ii = tid>>4, quad = tid&15
        float4 tot = make_float4(0.f, 0.f, 0.f, 0.f);
        #pragma unroll
        for (int ww = 0; ww < 16; ++ww) {
            float4 t = sRed[ww][tid];
            tot.x += t.x; tot.y += t.y; tot.z += t.z; tot.w += t.w;
        }
        int ii = tid >> 4, rr = tid & 15;
        *(float4*)&out[(i0 + ii) * B + blockIdx.x * JT + rr * 4] = tot;
    }
}

// ---------------- launch ----------------
extern "C" void kernel_launch(void* const* d_in, const int* in_sizes, int n_in,
                              void* d_out, int out_size)
{
    (void)n_in; (void)out_size;

    const float *e1_0, *e1_1, *e1_2, *e2_0, *e2_1, *e2_2;
    const float *c1_1, *c1_2, *c2_1, *c2_2;
    const float *a_1, *a_2, *b_1, *b_2;
    const float *link0, *link1;

    // Detect input ordering at runtime via element counts (see round-1 note).
    if (in_sizes[4] == 128) {
        // dict insertion order (interleaved per layer)
        e1_0 = (const float*)d_in[0];   e2_0 = (const float*)d_in[1];
        e1_1 = (const float*)d_in[6];   e2_1 = (const float*)d_in[7];
        e1_2 = (const float*)d_in[12];  e2_2 = (const float*)d_in[13];
        c1_1 = (const float*)d_in[8];   c2_1 = (const float*)d_in[9];
        c1_2 = (const float*)d_in[14];  c2_2 = (const float*)d_in[15];
        a_1  = (const float*)d_in[10];  b_1  = (const float*)d_in[11];
        a_2  = (const float*)d_in[16];  b_2  = (const float*)d_in[17];
        link0 = (const float*)d_in[18]; link1 = (const float*)d_in[19];
    } else {
        // function-signature order (grouped)
        e1_0 = (const float*)d_in[0];   e1_1 = (const float*)d_in[1];
        e1_2 = (const float*)d_in[2];
        e2_0 = (const float*)d_in[3];   e2_1 = (const float*)d_in[4];
        e2_2 = (const float*)d_in[5];
        c1_1 = (const float*)d_in[7];   c1_2 = (const float*)d_in[8];
        c2_1 = (const float*)d_in[10];  c2_2 = (const float*)d_in[11];
        a_1  = (const float*)d_in[13];  a_2  = (const float*)d_in[14];
        b_1  = (const float*)d_in[16];  b_2  = (const float*)d_in[17];
        link0 = (const float*)d_in[18]; link1 = (const float*)d_in[19];
    }

    // opt-in to 64 KB dynamic smem (function attribute, not an allocation)
    cudaFuncSetAttribute(avsl_main_kernel,
                         cudaFuncAttributeMaxDynamicSharedMemorySize,
                         2 * NH_BYTES);

    prep_kernel<<<299, 256>>>(e1_0, e1_1, e1_2, e2_0, e2_1, e2_2,
                              c1_1, c1_2, c2_1, c2_2, a_1, a_2, b_1, b_2,
                              link0, link1);

    dim3 grid(B / JT, B / IB);   // (8, 256)
    dim3 blk(8, 64);
    avsl_main_kernel<<<grid, blk, 2 * NH_BYTES>>>((float*)d_out);
}

// round 13
// speedup vs baseline: 1.2989x; 1.2989x over previous
#include <cuda_runtime.h>
#include <cuda_fp16.h>

#define B 512
#define D 128
#define JT 64            // j per work unit
#define NBLK 444         // persistent grid: 148 SMs x 3 blocks
#define NUNIT 4096       // (512 i) x (8 j-tiles)

// ---------------- device scratch (no allocation allowed) ----------------
__device__ float  g_e1n[3][B][D];     // normalized emb1, row-major [l][i][d]
__device__ __half g_e2nTh[3][D][B];   // normalized emb2, fp16, transposed [l][d][j]
__device__ float  g_c1p[2][B][D];     // cert1_{1,2} * 0.5*alpha_{1,2}
__device__ __half g_c2Th[2][D][B];    // cert2_{1,2}, fp16, transposed [l][d][j]
__device__ float  g_bp[2][D];         // 0.5*beta_{1,2}
__device__ uint4  g_wH[2][D];         // .x/.y/.z = broadcast half2 of w0..w2, .w = packed idx

__device__ __forceinline__ __half2 u2h(unsigned x) {
    __half2 h; *(unsigned*)&h = x; return h;
}
__device__ __forceinline__ unsigned h2u(__half2 h) {
    return *(unsigned*)&h;
}
__device__ __forceinline__ __half2 tanh2(__half2 x) {
    unsigned xi = h2u(x), yo;
    asm("tanh.approx.f16x2 %0, %1;" : "=r"(yo) : "r"(xi));
    return u2h(yo);
}
// r = s + P*(n-s),  n = (a-e2)^2,  P = 0.5*tanh(cp*c2+bp)+0.5   (all half2)
__device__ __forceinline__ __half2 blend2(__half2 ha, __half2 e2, __half2 cp,
                                          __half2 c2, __half2 bp, __half2 s,
                                          __half2 H05) {
    __half2 v = __hsub2(ha, e2);
    __half2 n = __hmul2(v, v);
    __half2 P = __hfma2(H05, tanh2(__hfma2(cp, c2, bp)), H05);
    return __hfma2(P, __hsub2(n, s), s);
}
// 3-term weighted sum of gathered half2s
__device__ __forceinline__ __half2 ws3(__half2 w0, __half2 w1, __half2 w2,
                                       unsigned a, unsigned b, unsigned c) {
    return __hfma2(w2, u2h(c), __hfma2(w1, u2h(b), __hmul2(w0, u2h(a))));
}

// ---------------- prep v2 (unchanged, proven) ----------------
__global__ __launch_bounds__(256) void prep_kernel(
    const float* __restrict__ e1_0, const float* __restrict__ e1_1, const float* __restrict__ e1_2,
    const float* __restrict__ e2_0, const float* __restrict__ e2_1, const float* __restrict__ e2_2,
    const float* __restrict__ c1_1, const float* __restrict__ c1_2,
    const float* __restrict__ c2_1, const float* __restrict__ c2_2,
    const float* __restrict__ a_1,  const float* __restrict__ a_2,
    const float* __restrict__ b_1,  const float* __restrict__ b_2,
    const float* __restrict__ link0, const float* __restrict__ link1)
{
    __shared__ float sm[64][129];
    __shared__ float part[4][64];
    __shared__ float sInv[64];

    const int bid = blockIdx.x;
    const int t   = threadIdx.x;

    if (bid < 40) {
        const bool isE = bid < 24;
        const int t2 = isE ? bid : bid - 24;
        const int l = t2 >> 3, rt = t2 & 7;
        const float* src = isE ? (l == 0 ? e2_0 : (l == 1 ? e2_1 : e2_2))
                               : (l == 0 ? c2_1 : c2_2);
        const int r0 = rt * 64;
        for (int idx = t; idx < 64 * 128; idx += 256) {
            int rr = idx >> 7, c = idx & 127;
            sm[rr][c] = src[(r0 + rr) * D + c];
        }
        __syncthreads();
        if (isE) {
            int qd = t >> 6, rr = t & 63;
            float ss = 0.f;
            #pragma unroll 8
            for (int c = qd * 32; c < qd * 32 + 32; ++c) {
                float x = sm[rr][c]; ss += x * x;
            }
            part[qd][rr] = ss;
            __syncthreads();
            if (t < 64) {
                float tot = part[0][t] + part[1][t] + part[2][t] + part[3][t];
                sInv[t] = 1.0f / fmaxf(sqrtf(tot), 1e-12f);
            }
        } else {
            if (t < 64) sInv[t] = 1.0f;
        }
        __syncthreads();
        __half (*dst)[B] = isE ? g_e2nTh[l] : g_c2Th[l];
        for (int idx = t; idx < 64 * 128; idx += 256) {
            int d2 = idx >> 6, rr = idx & 63;
            dst[d2][r0 + rr] = __float2half_rn(sm[rr][d2] * sInv[rr]);
        }
    } else if (bid < 232) {
        int rid = (bid - 40) * 8 + (t >> 5);
        int l = rid / 512, r = rid % 512;
        const float* src = (l == 0) ? e1_0 : (l == 1 ? e1_1 : e1_2);
        int lane = t & 31;
        float4 x = *(const float4*)&src[r * D + lane * 4];
        float ss = x.x * x.x + x.y * x.y + x.z * x.z + x.w * x.w;
        #pragma unroll
        for (int o = 16; o; o >>= 1) ss += __shfl_xor_sync(0xffffffffu, ss, o);
        float inv = 1.0f / fmaxf(sqrtf(ss), 1e-12f);
        float4 v = make_float4(x.x * inv, x.y * inv, x.z * inv, x.w * inv);
        *(float4*)&g_e1n[l][r][lane * 4] = v;
    } else if (bid < 296) {
        int base = (bid - 232) * 2048;
        #pragma unroll
        for (int k = 0; k < 8; ++k) {
            int idx = base + k * 256 + t;
            int l = idx >> 16;
            int rem = idx & 65535;
            int d2 = rem & 127;
            const float* c = l ? c1_2 : c1_1;
            const float* a = l ? a_2  : a_1;
            ((float*)g_c1p[l])[rem] = c[rem] * (0.5f * a[d2]);
        }
    } else if (bid == 296) {
        if (t < 128) {
            g_bp[0][t] = 0.5f * b_1[t];
            g_bp[1][t] = 0.5f * b_2[t];
        }
    } else {
        int m = bid - 297;
        if (t < 128) {
            int e = t;
            const float* L = m ? link1 : link0;
            float v0 = -1e30f, v1 = -1e30f, v2 = -1e30f;
            int   i0 = 0, i1 = 0, i2 = 0;
            for (int r = 0; r < D; ++r) {
                float w = L[r * D + e];
                if (w > v0)      { v2 = v1; i2 = i1; v1 = v0; i1 = i0; v0 = w; i0 = r; }
                else if (w > v1) { v2 = v1; i2 = i1; v1 = w;  i1 = r; }
                else if (w > v2) { v2 = w;  i2 = r; }
            }
            float inv = 1.0f / (v0 + v1 + v2 + 1e-8f);
            unsigned h0 = (unsigned)__half_as_ushort(__float2half_rn(v0 * inv));
            unsigned h1 = (unsigned)__half_as_ushort(__float2half_rn(v1 * inv));
            unsigned h2 = (unsigned)__half_as_ushort(__float2half_rn(v2 * inv));
            g_wH[m][e] = make_uint4(h0 * 0x10001u, h1 * 0x10001u, h2 * 0x10001u,
                                    (unsigned)i0 | ((unsigned)i1 << 8) | ((unsigned)i2 << 16));
        }
    }
}

// ---------------- fused similarity kernel (round-10 body, persistent) -------
// 444 persistent blocks (3/SM), each looping over a contiguous chunk of 9-10
// (i, j-tile) units. W staged once/block; sIh restaged only when i changes.
// Unit body identical to the proven round-10 kernel: nh double buffer A->B,
// all LDS.128 conflict-free (8-lane group = one full 128B row), half2 math.
__global__ __launch_bounds__(512, 3) void avsl_main_kernel(float* __restrict__ out)
{
    __shared__ union {
        struct { __half A[D][JT]; __half Bb[D][JT]; } nh;  // 32 KB
        float4 sRed[16][16];     // 4 KB, aliased over nh.A (dead at reduction)
    } u;
    __shared__ uint4    sW[2][D];    // 4 KB
    __shared__ unsigned sIh[5][D];   // 2.5 KB
    __shared__ unsigned sBPh[2][D];  // 1 KB

    const int q   = threadIdx.x;     // 0..7  (j-oct)
    const int g   = threadIdx.y;     // 0..63 (channel pair)
    const int tid = g * 8 + q;
    const int bid = blockIdx.x;

    // stage W + bp once per persistent block
    if (tid < 2 * D) {
        ((uint4*)sW)[tid] = ((const uint4*)g_wH)[tid];
        ((unsigned*)sBPh)[tid] = h2u(__float2half2_rn(((const float*)g_bp)[tid]));
    }

    // contiguous chunk: first 100 blocks get 10 units, rest 9
    const int base = bid * 9 + (bid < 100 ? bid : 100);
    const int cnt  = 9 + (bid < 100 ? 1 : 0);
    int last_i = -1;

    const __half2 H05 = __float2half2_rn(0.5f);
    const int e0 = g * 2, e1c = g * 2 + 1;

    for (int it = 0; it < cnt; ++it) {
        const int unit = base + it;
        const int i  = unit >> 3;
        const int jj = (unit & 7) * JT + q * 8;

        if (i != last_i) {
            for (int t = tid; t < 5 * D; t += 512) {
                int seg = t >> 7, d = t & 127;
                float v = (seg < 3) ? g_e1n[seg][i][d] : g_c1p[seg - 3][i][d];
                sIh[seg][d] = h2u(__float2half2_rn(v));
            }
            last_i = i;
        }
        __syncthreads();   // (1) staging done + prior-unit sRed reads complete

        // ---- layer 0 -> nh.A ----
        {
            uint4 ea = *(const uint4*)&g_e2nTh[0][e0][jj];
            uint4 eb = *(const uint4*)&g_e2nTh[0][e1c][jj];
            __half2 h0 = u2h(sIh[0][e0]), h1 = u2h(sIh[0][e1c]);
            uint4 ra, rb;
            __half2 v;
            v = __hsub2(h0, u2h(ea.x)); ra.x = h2u(__hmul2(v, v));
            v = __hsub2(h0, u2h(ea.y)); ra.y = h2u(__hmul2(v, v));
            v = __hsub2(h0, u2h(ea.z)); ra.z = h2u(__hmul2(v, v));
            v = __hsub2(h0, u2h(ea.w)); ra.w = h2u(__hmul2(v, v));
            v = __hsub2(h1, u2h(eb.x)); rb.x = h2u(__hmul2(v, v));
            v = __hsub2(h1, u2h(eb.y)); rb.y = h2u(__hmul2(v, v));
            v = __hsub2(h1, u2h(eb.z)); rb.z = h2u(__hmul2(v, v));
            v = __hsub2(h1, u2h(eb.w)); rb.w = h2u(__hmul2(v, v));
            *(uint4*)&u.nh.A[e0][q * 8]  = ra;
            *(uint4*)&u.nh.A[e1c][q * 8] = rb;
        }
        __syncthreads();   // (2)

        // ---- layer 1: gather nh.A -> write nh.B ----
        #pragma unroll
        for (int k = 0; k < 2; ++k) {
            const int e = g * 2 + k;
            const uint4 W = sW[0][e];
            const __half2 w0 = u2h(W.x), w1 = u2h(W.y), w2 = u2h(W.z);
            const int o0 = (int)(W.w & 255u) * 8;
            const int o1 = (int)((W.w >> 8) & 255u) * 8;
            const int o2 = (int)((W.w >> 16) & 255u) * 8;
            const uint4* nb = (const uint4*)u.nh.A;
            uint4 r0 = nb[o0 + q], r1 = nb[o1 + q], r2 = nb[o2 + q];
            uint4 e2u = *(const uint4*)&g_e2nTh[1][e][jj];
            uint4 c2u = *(const uint4*)&g_c2Th[0][e][jj];
            __half2 ha = u2h(sIh[1][e]);
            __half2 cp = u2h(sIh[3][e]);
            __half2 bp = u2h(sBPh[0][e]);
            uint4 res;
            res.x = h2u(blend2(ha, u2h(e2u.x), cp, u2h(c2u.x), bp,
                               ws3(w0, w1, w2, r0.x, r1.x, r2.x), H05));
            res.y = h2u(blend2(ha, u2h(e2u.y), cp, u2h(c2u.y), bp,
                               ws3(w0, w1, w2, r0.y, r1.y, r2.y), H05));
            res.z = h2u(blend2(ha, u2h(e2u.z), cp, u2h(c2u.z), bp,
                               ws3(w0, w1, w2, r0.z, r1.z, r2.z), H05));
            res.w = h2u(blend2(ha, u2h(e2u.w), cp, u2h(c2u.w), bp,
                               ws3(w0, w1, w2, r0.w, r1.w, r2.w), H05));
            *(uint4*)&u.nh.Bb[e][q * 8] = res;
        }
        __syncthreads();   // (3)

        // ---- layer 2: gather nh.B + channel accumulation (fp32 acc) ----
        float4 a0 = make_float4(0.f, 0.f, 0.f, 0.f);
        float4 a1 = make_float4(0.f, 0.f, 0.f, 0.f);
        #pragma unroll
        for (int k = 0; k < 2; ++k) {
            const int e = g * 2 + k;
            const uint4 W = sW[1][e];
            const __half2 w0 = u2h(W.x), w1 = u2h(W.y), w2 = u2h(W.z);
            const int o0 = (int)(W.w & 255u) * 8;
            const int o1 = (int)((W.w >> 8) & 255u) * 8;
            const int o2 = (int)((W.w >> 16) & 255u) * 8;
            const uint4* nb = (const uint4*)u.nh.Bb;
            uint4 r0 = nb[o0 + q], r1 = nb[o1 + q], r2 = nb[o2 + q];
            uint4 e2u = *(const uint4*)&g_e2nTh[2][e][jj];
            uint4 c2u = *(const uint4*)&g_c2Th[1][e][jj];
            __half2 ha = u2h(sIh[2][e]);
            __half2 cp = u2h(sIh[4][e]);
            __half2 bp = u2h(sBPh[1][e]);
            __half2 rA = blend2(ha, u2h(e2u.x), cp, u2h(c2u.x), bp,
                                ws3(w0, w1, w2, r0.x, r1.x, r2.x), H05);
            __half2 rB = blend2(ha, u2h(e2u.y), cp, u2h(c2u.y), bp,
                                ws3(w0, w1, w2, r0.y, r1.y, r2.y), H05);
            __half2 rC = blend2(ha, u2h(e2u.z), cp, u2h(c2u.z), bp,
                                ws3(w0, w1, w2, r0.z, r1.z, r2.z), H05);
            __half2 rD = blend2(ha, u2h(e2u.w), cp, u2h(c2u.w), bp,
                                ws3(w0, w1, w2, r0.w, r1.w, r2.w), H05);
            float2 fA = __half22float2(rA), fB = __half22float2(rB);
            float2 fC = __half22float2(rC), fD = __half22float2(rD);
            a0.x += fA.x; a0.y += fA.y; a0.z += fB.x; a0.w += fB.y;
            a1.x += fC.x; a1.y += fC.y; a1.z += fD.x; a1.w += fD.y;
        }

        // fold the 4 channel-pair groups sharing a warp (8-lane groups)
        a0.x += __shfl_down_sync(0xffffffffu, a0.x, 16);
        a0.y += __shfl_down_sync(0xffffffffu, a0.y, 16);
        a0.z += __shfl_down_sync(0xffffffffu, a0.z, 16);
        a0.w += __shfl_down_sync(0xffffffffu, a0.w, 16);
        a1.x += __shfl_down_sync(0xffffffffu, a1.x, 16);
        a1.y += __shfl_down_sync(0xffffffffu, a1.y, 16);
        a1.z += __shfl_down_sync(0xffffffffu, a1.z, 16);
        a1.w += __shfl_down_sync(0xffffffffu, a1.w, 16);
        a0.x += __shfl_down_sync(0xffffffffu, a0.x, 8);
        a0.y += __shfl_down_sync(0xffffffffu, a0.y, 8);
        a0.z += __shfl_down_sync(0xffffffffu, a0.z, 8);
        a0.w += __shfl_down_sync(0xffffffffu, a0.w, 8);
        a1.x += __shfl_down_sync(0xffffffffu, a1.x, 8);
        a1.y += __shfl_down_sync(0xffffffffu, a1.y, 8);
        a1.z += __shfl_down_sync(0xffffffffu, a1.z, 8);
        a1.w += __shfl_down_sync(0xffffffffu, a1.w, 8);
        __syncthreads();   // (4) — all nh reads done: sRed alias is safe
        const int w = tid >> 5, lane = tid & 31;
        if (lane < 8) {
            u.sRed[w][lane * 2]     = a0;
            u.sRed[w][lane * 2 + 1] = a1;
        }
        __syncthreads();   // (5)
        if (tid < 16) {
            float4 tot = make_float4(0.f, 0.f, 0.f, 0.f);
            #pragma unroll
            for (int ww = 0; ww < 16; ++ww) {
                float4 t = u.sRed[ww][tid];
                tot.x += t.x; tot.y += t.y; tot.z += t.z; tot.w += t.w;
            }
            *(float4*)&out[i * B + (unit & 7) * JT + tid * 4] = tot;
        }
    }
}

// ---------------- launch ----------------
extern "C" void kernel_launch(void* const* d_in, const int* in_sizes, int n_in,
                              void* d_out, int out_size)
{
    (void)n_in; (void)out_size;

    const float *e1_0, *e1_1, *e1_2, *e2_0, *e2_1, *e2_2;
    const float *c1_1, *c1_2, *c2_1, *c2_2;
    const float *a_1, *a_2, *b_1, *b_2;
    const float *link0, *link1;

    // Detect input ordering at runtime via element counts (see round-1 note).
    if (in_sizes[4] == 128) {
        // dict insertion order (interleaved per layer)
        e1_0 = (const float*)d_in[0];   e2_0 = (const float*)d_in[1];
        e1_1 = (const float*)d_in[6];   e2_1 = (const float*)d_in[7];
        e1_2 = (const float*)d_in[12];  e2_2 = (const float*)d_in[13];
        c1_1 = (const float*)d_in[8];   c2_1 = (const float*)d_in[9];
        c1_2 = (const float*)d_in[14];  c2_2 = (const float*)d_in[15];
        a_1  = (const float*)d_in[10];  b_1  = (const float*)d_in[11];
        a_2  = (const float*)d_in[16];  b_2  = (const float*)d_in[17];
        link0 = (const float*)d_in[18]; link1 = (const float*)d_in[19];
    } else {
        // function-signature order (grouped)
        e1_0 = (const float*)d_in[0];   e1_1 = (const float*)d_in[1];
        e1_2 = (const float*)d_in[2];
        e2_0 = (const float*)d_in[3];   e2_1 = (const float*)d_in[4];
        e2_2 = (const float*)d_in[5];
        c1_1 = (const float*)d_in[7];   c1_2 = (const float*)d_in[8];
        c2_1 = (const float*)d_in[10];  c2_2 = (const float*)d_in[11];
        a_1  = (const float*)d_in[13];  a_2  = (const float*)d_in[14];
        b_1  = (const float*)d_in[16];  b_2  = (const float*)d_in[17];
        link0 = (const float*)d_in[18]; link1 = (const float*)d_in[19];
    }

    prep_kernel<<<299, 256>>>(e1_0, e1_1, e1_2, e2_0, e2_1, e2_2,
                              c1_1, c1_2, c2_1, c2_2, a_1, a_2, b_1, b_2,
                              link0, link1);

    dim3 blk(8, 64);
    avsl_main_kernel<<<NBLK, blk>>>((float*)d_out);
}